// round 15
// baseline (speedup 1.0000x reference)
#include <cuda_runtime.h>
#include <math.h>

#define B_    32
#define NIN   2312
#define NHID  512
#define NOUT  10
#define T_    350
#define TK    100
#define THETA 10.0f

// refractory IIR constants
#define D_REF 0.36787944117144233f
#define C_REF (-5.43656365691809f)

// psp alpha-kernel IIR constants: eps[k] = (e/10) * k * d^k, d = e^{-0.1}
#define D_SR  0.90483741803595952f    // exp(-0.1)
#define C_E   0.27182818284590452f    // e/10
#define K2C   1.2340980408667956e-05f // C_E * exp(-10)
#define K3C   1.2340980408667956e-03f // 100 * C_E * exp(-10)

// sparse index structure
#define NCH   8
#define CHUNK 289
#define CAPC  96
#define NCOL  (B_ * T_)           // 11200

#define R1    (B_ * NHID)         // 16384
#define R2    (B_ * NOUT)         // 320

// fused prep kernel geometry
#define NTRB  (73 * 16)           // 1168 transpose tiles
#define NBLB  (2 * NCH * B_)      // 512 build blocks

// ------------------------- static device scratch ---------------------------
__device__ float g_W1T[(size_t)NIN * NHID];                 // [i, o]
__device__ unsigned short g_idx[(size_t)NCOL * NCH * CAPC];
__device__ int            g_cnt[(size_t)NCOL * NCH];
__device__ float g_y1[(size_t)T_ * R1];   // t-major: [t][b*512+o]
__device__ float g_s1[(size_t)T_ * R1];   // t-major
__device__ float g_z2[(size_t)T_ * R2];   // t-major

// ---------------------------------------------------------------------------
// Fused prep: W1 transpose tiles (blocks [0, 1168)) + active-index build
// (blocks [1168, 1168+512)).
// ---------------------------------------------------------------------------
__global__ __launch_bounds__(256) void prep_kernel(
    const float* __restrict__ W1, const float* __restrict__ X)
{
    const int bid = blockIdx.x;

    if (bid < NTRB) {
        __shared__ float tile[32][33];
        const int i0 = (bid % 73) * 32;
        const int o0 = (bid / 73) * 32;
        const int lx = threadIdx.x & 31;
        const int ly = threadIdx.x >> 5;

#pragma unroll
        for (int r = 0; r < 32; r += 8) {
            int o = o0 + ly + r;
            int i = i0 + lx;
            tile[ly + r][lx] = (i < NIN) ? W1[(size_t)o * NIN + i] : 0.0f;
        }
        __syncthreads();
#pragma unroll
        for (int r = 0; r < 32; r += 8) {
            int i = i0 + ly + r;
            int o = o0 + lx;
            if (i < NIN) g_W1T[(size_t)i * NHID + o] = tile[lx][ly + r];
        }
    } else {
        const int bid2 = bid - NTRB;
        const int tseg = bid2 & 1;
        const int c    = (bid2 >> 1) & 7;
        const int b    = bid2 >> 4;
        const int t    = tseg * 256 + threadIdx.x;
        if (t >= T_) return;

        const int col = b * T_ + t;
        unsigned short* dst = g_idx + ((size_t)col * NCH + c) * CAPC;
        const float* __restrict__ xb = X + (size_t)b * NIN * T_ + t;

        int cnt = 0;
        const int i0 = c * CHUNK;
#pragma unroll 4
        for (int i = i0; i < i0 + CHUNK; i++) {
            float v = xb[(size_t)i * T_];
            if (v != 0.0f) {
                if (cnt < CAPC) dst[cnt] = (unsigned short)i;
                cnt++;
            }
        }
        g_cnt[col * NCH + c] = (cnt < CAPC) ? cnt : CAPC;
    }
}

// ---------------------------------------------------------------------------
// Sparse gather-accumulate (proven at the L1/L2 joint wall):
//   y1T[t][b*512 + :] = sum_{i active(b,t)} W1T[i,:]
// ---------------------------------------------------------------------------
__global__ __launch_bounds__(128) void sparse_accum_kernel() {
    const int col = blockIdx.x;
    const int tid = threadIdx.x;

    __shared__ unsigned short sidx[NCH * CAPC];
    __shared__ int psum[NCH + 1];

    if (tid == 0) {
        int s = 0;
        psum[0] = 0;
#pragma unroll
        for (int c = 0; c < NCH; c++) { s += g_cnt[col * NCH + c]; psum[c + 1] = s; }
    }
    __syncthreads();

    if (tid < NCH) {
        const int c = tid;
        const int n = psum[c + 1] - psum[c];
        const unsigned short* src = g_idx + ((size_t)col * NCH + c) * CAPC;
        unsigned short* d = sidx + psum[c];
        for (int k = 0; k < n; k++) d[k] = src[k];
    }
    __syncthreads();

    const int tot = psum[NCH];
    const float4* __restrict__ W = (const float4*)g_W1T;

    float4 acc = make_float4(0.f, 0.f, 0.f, 0.f);
    int k = 0;
    for (; k + 4 <= tot; k += 4) {
        int i0 = sidx[k], i1 = sidx[k + 1], i2 = sidx[k + 2], i3 = sidx[k + 3];
        float4 w0 = W[(size_t)i0 * 128 + tid];
        float4 w1 = W[(size_t)i1 * 128 + tid];
        float4 w2 = W[(size_t)i2 * 128 + tid];
        float4 w3 = W[(size_t)i3 * 128 + tid];
        acc.x += w0.x; acc.y += w0.y; acc.z += w0.z; acc.w += w0.w;
        acc.x += w1.x; acc.y += w1.y; acc.z += w1.z; acc.w += w1.w;
        acc.x += w2.x; acc.y += w2.y; acc.z += w2.z; acc.w += w2.w;
        acc.x += w3.x; acc.y += w3.y; acc.z += w3.z; acc.w += w3.w;
    }
    for (; k < tot; k++) {
        float4 w0 = W[(size_t)sidx[k] * 128 + tid];
        acc.x += w0.x; acc.y += w0.y; acc.z += w0.z; acc.w += w0.w;
    }

    const int b = col / T_;
    const int t = col - b * T_;
    float4* dst = (float4*)(g_y1 + (size_t)t * R1 + b * NHID);
    dst[tid] = acc;
}

// ---------------------------------------------------------------------------
// Scan v6 (proven): t-major, compile-time stride, double-buffered prefetch.
// ---------------------------------------------------------------------------
template<int STRIDE, bool TMAJOR_OUT>
__global__ __launch_bounds__(64) void iir_scan_kernel(
    const float* __restrict__ Y, float* __restrict__ Sout)
{
    const int row = blockIdx.x * 64 + threadIdx.x;
    const float* __restrict__ yp = Y + row;

    float P = 0.f, S = 0.f;
    float P2 = 0.f, S2 = 0.f;
    float a = 0.f, bst = 0.f;

    float yv[10], yo[10], nyv[10], nyo[10], sb[10];

#pragma unroll
    for (int k = 0; k < 10; k++) yv[k] = yp[(size_t)k * STRIDE];
#pragma unroll
    for (int k = 0; k < 10; k++) yo[k] = 0.0f;

    for (int c = 0; c < 35; c++) {
        const int t0 = c * 10;

        if (c < 34) {
            const int tn = t0 + 10;
#pragma unroll
            for (int k = 0; k < 10; k++)
                nyv[k] = yp[(size_t)(tn + k) * STRIDE];
            if (c + 1 >= 10) {
#pragma unroll
                for (int k = 0; k < 10; k++)
                    nyo[k] = yp[(size_t)(tn + k - TK) * STRIDE];
            } else {
#pragma unroll
                for (int k = 0; k < 10; k++) nyo[k] = 0.0f;
            }
        }

#pragma unroll
        for (int k = 0; k < 10; k++) {
            const float dP2 = D_SR * P2;
            S2 = fmaf(D_SR, S2, dP2);
            P2 = dP2 + yo[k];
            const float corr = fmaf(-K2C, S2, -K3C * P2);

            const float dP = D_SR * P;
            S = fmaf(D_SR, S, dP);
            P = dP + yv[k];

            const float u = fmaf(C_E, S, fmaf(C_REF, bst, corr));
            const float s = (u >= THETA) ? 1.0f : 0.0f;
            const float g = D_REF * a;
            bst = fmaf(D_REF, bst, g);
            a   = g + s;
            sb[k] = s;
        }

        if (TMAJOR_OUT) {
#pragma unroll
            for (int k = 0; k < 10; k++)
                Sout[(size_t)(t0 + k) * STRIDE + row] = sb[k];
        } else {
#pragma unroll
            for (int k = 0; k < 10; k++)
                Sout[(size_t)row * T_ + t0 + k] = sb[k];
        }

#pragma unroll
        for (int k = 0; k < 10; k++) { yv[k] = nyv[k]; yo[k] = nyo[k]; }
    }
}

// ---------------------------------------------------------------------------
// GEMM2 v2: warp handles 4 consecutive t-columns of one b.
// Each W2 LDS.128 feeds 4 dot-products (4x less L1 crossbar than v1);
// 352 blocks instead of 1400 (4x less W2 re-staging).
// ---------------------------------------------------------------------------
__global__ __launch_bounds__(256) void gemm2_kernel(
    const float* __restrict__ W2, const float* __restrict__ S1T,
    float* __restrict__ Z2T)
{
    __shared__ float w2s[NOUT * NHID];   // 20 KB
    for (int i = threadIdx.x; i < NOUT * NHID; i += 256) w2s[i] = W2[i];
    __syncthreads();

    const int warp = threadIdx.x >> 5;
    const int lane = threadIdx.x & 31;
    const int b    = blockIdx.y;
    const int t0   = blockIdx.x * 32 + warp * 4;   // first of 4 columns

    const float4* __restrict__ wv = (const float4*)w2s;

    float acc[4][NOUT];
#pragma unroll
    for (int c = 0; c < 4; c++)
#pragma unroll
        for (int j = 0; j < NOUT; j++) acc[c][j] = 0.0f;

#pragma unroll
    for (int p = 0; p < 4; p++) {
        float4 v[4];
#pragma unroll
        for (int c = 0; c < 4; c++) {
            const int t = t0 + c;
            v[c] = (t < T_)
                 ? ((const float4*)(S1T + (size_t)t * R1 + b * NHID))[p * 32 + lane]
                 : make_float4(0.f, 0.f, 0.f, 0.f);
        }
#pragma unroll
        for (int j = 0; j < NOUT; j++) {
            const float4 w = wv[j * 128 + p * 32 + lane];
#pragma unroll
            for (int c = 0; c < 4; c++)
                acc[c][j] += w.x * v[c].x + w.y * v[c].y + w.z * v[c].z + w.w * v[c].w;
        }
    }

#pragma unroll
    for (int c = 0; c < 4; c++) {
#pragma unroll
        for (int j = 0; j < NOUT; j++) {
#pragma unroll
            for (int sh = 16; sh > 0; sh >>= 1)
                acc[c][j] += __shfl_xor_sync(0xffffffffu, acc[c][j], sh);
        }
        const int t = t0 + c;
        if (t < T_ && lane < NOUT) {
            float outv = 0.0f;
#pragma unroll
            for (int j = 0; j < NOUT; j++)
                outv = (lane == j) ? acc[c][j] : outv;
            Z2T[(size_t)t * R2 + b * NOUT + lane] = outv;
        }
    }
}

// ---------------------------------------------------------------------------
extern "C" void kernel_launch(void* const* d_in, const int* in_sizes, int n_in,
                              void* d_out, int out_size)
{
    const float* spikeInput = (const float*)d_in[0];  // [32, 2312, 350]
    const float* W1         = (const float*)d_in[1];  // [512, 2312]
    const float* W2         = (const float*)d_in[2];  // [10, 512]
    float*       out        = (float*)d_out;          // [32, 10, 350]

    float *y1p, *s1p, *z2p;
    cudaGetSymbolAddress((void**)&y1p, g_y1);
    cudaGetSymbolAddress((void**)&s1p, g_s1);
    cudaGetSymbolAddress((void**)&z2p, g_z2);

    // #1: fused transpose + index build
    prep_kernel<<<NTRB + NBLB, 256>>>(W1, spikeInput);

    // #2: sparse gather-accumulate (dominant, at its wall)
    sparse_accum_kernel<<<NCOL, 128>>>();

    // #3: layer-1 scan
    iir_scan_kernel<R1, true><<<R1 / 64, 64>>>(y1p, s1p);

    // #4: dense layer 2 (profiled)
    dim3 g2((T_ + 31) / 32, B_);              // (11, 32)
    gemm2_kernel<<<g2, 256>>>(W2, s1p, z2p);

    // #5: layer-2 scan -> final output
    iir_scan_kernel<R2, false><<<R2 / 64, 64>>>(z2p, out);
}

// round 16
// speedup vs baseline: 1.0093x; 1.0093x over previous
#include <cuda_runtime.h>
#include <math.h>

#define B_    32
#define NIN   2312
#define NHID  512
#define NOUT  10
#define T_    350
#define TK    100
#define THETA 10.0f

// refractory IIR constants
#define D_REF 0.36787944117144233f
#define C_REF (-5.43656365691809f)

// psp alpha-kernel IIR constants: eps[k] = (e/10) * k * d^k, d = e^{-0.1}
#define D_SR  0.90483741803595952f    // exp(-0.1)
#define C_E   0.27182818284590452f    // e/10
#define K2C   1.2340980408667956e-05f // C_E * exp(-10)
#define K3C   1.2340980408667956e-03f // 100 * C_E * exp(-10)

// sparse index structure
#define NCH   8
#define CHUNK 289
#define CAPC  96
#define NCOL  (B_ * T_)           // 11200

#define R1    (B_ * NHID)         // 16384
#define R2    (B_ * NOUT)         // 320

// fused prep kernel geometry
#define NTRB  (73 * 16)           // 1168 transpose tiles
#define NBLB  (2 * NCH * B_)      // 512 build blocks

// ------------------------- static device scratch ---------------------------
__device__ float g_W1T[(size_t)NIN * NHID];                 // [i, o]
__device__ unsigned short g_idx[(size_t)NCOL * NCH * CAPC];
__device__ int            g_cnt[(size_t)NCOL * NCH];
__device__ float g_y1[(size_t)T_ * R1];   // t-major: [t][b*512+o]
__device__ float g_s1[(size_t)T_ * R1];   // t-major
__device__ float g_z2[(size_t)T_ * R2];   // t-major

// ---------------------------------------------------------------------------
// Fused prep: W1 transpose tiles (blocks [0, 1168)) + active-index build
// (blocks [1168, 1168+512)).
// ---------------------------------------------------------------------------
__global__ __launch_bounds__(256) void prep_kernel(
    const float* __restrict__ W1, const float* __restrict__ X)
{
    const int bid = blockIdx.x;

    if (bid < NTRB) {
        __shared__ float tile[32][33];
        const int i0 = (bid % 73) * 32;
        const int o0 = (bid / 73) * 32;
        const int lx = threadIdx.x & 31;
        const int ly = threadIdx.x >> 5;

#pragma unroll
        for (int r = 0; r < 32; r += 8) {
            int o = o0 + ly + r;
            int i = i0 + lx;
            tile[ly + r][lx] = (i < NIN) ? W1[(size_t)o * NIN + i] : 0.0f;
        }
        __syncthreads();
#pragma unroll
        for (int r = 0; r < 32; r += 8) {
            int i = i0 + ly + r;
            int o = o0 + lx;
            if (i < NIN) g_W1T[(size_t)i * NHID + o] = tile[lx][ly + r];
        }
    } else {
        const int bid2 = bid - NTRB;
        const int tseg = bid2 & 1;
        const int c    = (bid2 >> 1) & 7;
        const int b    = bid2 >> 4;
        const int t    = tseg * 256 + threadIdx.x;
        if (t >= T_) return;

        const int col = b * T_ + t;
        unsigned short* dst = g_idx + ((size_t)col * NCH + c) * CAPC;
        const float* __restrict__ xb = X + (size_t)b * NIN * T_ + t;

        int cnt = 0;
        const int i0 = c * CHUNK;
#pragma unroll 4
        for (int i = i0; i < i0 + CHUNK; i++) {
            float v = xb[(size_t)i * T_];
            if (v != 0.0f) {
                if (cnt < CAPC) dst[cnt] = (unsigned short)i;
                cnt++;
            }
        }
        g_cnt[col * NCH + c] = (cnt < CAPC) ? cnt : CAPC;
    }
}

// ---------------------------------------------------------------------------
// Sparse gather-accumulate (proven at the L1/L2 joint wall):
//   y1T[t][b*512 + :] = sum_{i active(b,t)} W1T[i,:]
// ---------------------------------------------------------------------------
__global__ __launch_bounds__(128) void sparse_accum_kernel() {
    const int col = blockIdx.x;
    const int tid = threadIdx.x;

    __shared__ unsigned short sidx[NCH * CAPC];
    __shared__ int psum[NCH + 1];

    if (tid == 0) {
        int s = 0;
        psum[0] = 0;
#pragma unroll
        for (int c = 0; c < NCH; c++) { s += g_cnt[col * NCH + c]; psum[c + 1] = s; }
    }
    __syncthreads();

    if (tid < NCH) {
        const int c = tid;
        const int n = psum[c + 1] - psum[c];
        const unsigned short* src = g_idx + ((size_t)col * NCH + c) * CAPC;
        unsigned short* d = sidx + psum[c];
        for (int k = 0; k < n; k++) d[k] = src[k];
    }
    __syncthreads();

    const int tot = psum[NCH];
    const float4* __restrict__ W = (const float4*)g_W1T;

    float4 acc = make_float4(0.f, 0.f, 0.f, 0.f);
    int k = 0;
    for (; k + 4 <= tot; k += 4) {
        int i0 = sidx[k], i1 = sidx[k + 1], i2 = sidx[k + 2], i3 = sidx[k + 3];
        float4 w0 = W[(size_t)i0 * 128 + tid];
        float4 w1 = W[(size_t)i1 * 128 + tid];
        float4 w2 = W[(size_t)i2 * 128 + tid];
        float4 w3 = W[(size_t)i3 * 128 + tid];
        acc.x += w0.x; acc.y += w0.y; acc.z += w0.z; acc.w += w0.w;
        acc.x += w1.x; acc.y += w1.y; acc.z += w1.z; acc.w += w1.w;
        acc.x += w2.x; acc.y += w2.y; acc.z += w2.z; acc.w += w2.w;
        acc.x += w3.x; acc.y += w3.y; acc.z += w3.z; acc.w += w3.w;
    }
    for (; k < tot; k++) {
        float4 w0 = W[(size_t)sidx[k] * 128 + tid];
        acc.x += w0.x; acc.y += w0.y; acc.z += w0.z; acc.w += w0.w;
    }

    const int b = col / T_;
    const int t = col - b * T_;
    float4* dst = (float4*)(g_y1 + (size_t)t * R1 + b * NHID);
    dst[tid] = acc;
}

// ---------------------------------------------------------------------------
// Scan v6 (proven): t-major, compile-time stride, double-buffered prefetch.
// ---------------------------------------------------------------------------
template<int STRIDE, bool TMAJOR_OUT>
__global__ __launch_bounds__(64) void iir_scan_kernel(
    const float* __restrict__ Y, float* __restrict__ Sout)
{
    const int row = blockIdx.x * 64 + threadIdx.x;
    const float* __restrict__ yp = Y + row;

    float P = 0.f, S = 0.f;
    float P2 = 0.f, S2 = 0.f;
    float a = 0.f, bst = 0.f;

    float yv[10], yo[10], nyv[10], nyo[10], sb[10];

#pragma unroll
    for (int k = 0; k < 10; k++) yv[k] = yp[(size_t)k * STRIDE];
#pragma unroll
    for (int k = 0; k < 10; k++) yo[k] = 0.0f;

    for (int c = 0; c < 35; c++) {
        const int t0 = c * 10;

        if (c < 34) {
            const int tn = t0 + 10;
#pragma unroll
            for (int k = 0; k < 10; k++)
                nyv[k] = yp[(size_t)(tn + k) * STRIDE];
            if (c + 1 >= 10) {
#pragma unroll
                for (int k = 0; k < 10; k++)
                    nyo[k] = yp[(size_t)(tn + k - TK) * STRIDE];
            } else {
#pragma unroll
                for (int k = 0; k < 10; k++) nyo[k] = 0.0f;
            }
        }

#pragma unroll
        for (int k = 0; k < 10; k++) {
            const float dP2 = D_SR * P2;
            S2 = fmaf(D_SR, S2, dP2);
            P2 = dP2 + yo[k];
            const float corr = fmaf(-K2C, S2, -K3C * P2);

            const float dP = D_SR * P;
            S = fmaf(D_SR, S, dP);
            P = dP + yv[k];

            const float u = fmaf(C_E, S, fmaf(C_REF, bst, corr));
            const float s = (u >= THETA) ? 1.0f : 0.0f;
            const float g = D_REF * a;
            bst = fmaf(D_REF, bst, g);
            a   = g + s;
            sb[k] = s;
        }

        if (TMAJOR_OUT) {
#pragma unroll
            for (int k = 0; k < 10; k++)
                Sout[(size_t)(t0 + k) * STRIDE + row] = sb[k];
        } else {
#pragma unroll
            for (int k = 0; k < 10; k++)
                Sout[(size_t)row * T_ + t0 + k] = sb[k];
        }

#pragma unroll
        for (int k = 0; k < 10; k++) { yv[k] = nyv[k]; yo[k] = nyo[k]; }
    }
}

// ---------------------------------------------------------------------------
// GEMM2 v1.5: warp handles 2 consecutive t-columns of one b.
// Each W2 LDS.128 feeds 2 dot-products (half the L1 crossbar of v1) while
// register pressure stays low enough for ~full occupancy (unlike 4-col v2).
// ---------------------------------------------------------------------------
__global__ __launch_bounds__(256) void gemm2_kernel(
    const float* __restrict__ W2, const float* __restrict__ S1T,
    float* __restrict__ Z2T)
{
    __shared__ float w2s[NOUT * NHID];   // 20 KB
    for (int i = threadIdx.x; i < NOUT * NHID; i += 256) w2s[i] = W2[i];
    __syncthreads();

    const int warp = threadIdx.x >> 5;
    const int lane = threadIdx.x & 31;
    const int b    = blockIdx.y;
    const int t0   = blockIdx.x * 16 + warp * 2;   // first of 2 columns

    const float4* __restrict__ wv = (const float4*)w2s;

    float acc0[NOUT], acc1[NOUT];
#pragma unroll
    for (int j = 0; j < NOUT; j++) { acc0[j] = 0.0f; acc1[j] = 0.0f; }

    const int t1 = t0 + 1;
    const bool ok0 = (t0 < T_);
    const bool ok1 = (t1 < T_);
    const float4* __restrict__ sv0 = (const float4*)(S1T + (size_t)t0 * R1 + b * NHID);
    const float4* __restrict__ sv1 = (const float4*)(S1T + (size_t)t1 * R1 + b * NHID);

#pragma unroll
    for (int p = 0; p < 4; p++) {
        const float4 v0 = ok0 ? sv0[p * 32 + lane] : make_float4(0.f, 0.f, 0.f, 0.f);
        const float4 v1 = ok1 ? sv1[p * 32 + lane] : make_float4(0.f, 0.f, 0.f, 0.f);
#pragma unroll
        for (int j = 0; j < NOUT; j++) {
            const float4 w = wv[j * 128 + p * 32 + lane];
            acc0[j] += w.x * v0.x + w.y * v0.y + w.z * v0.z + w.w * v0.w;
            acc1[j] += w.x * v1.x + w.y * v1.y + w.z * v1.z + w.w * v1.w;
        }
    }

#pragma unroll
    for (int j = 0; j < NOUT; j++) {
#pragma unroll
        for (int sh = 16; sh > 0; sh >>= 1) {
            acc0[j] += __shfl_xor_sync(0xffffffffu, acc0[j], sh);
            acc1[j] += __shfl_xor_sync(0xffffffffu, acc1[j], sh);
        }
    }

    if (ok0 && lane < NOUT) {
        float outv = acc0[0];
#pragma unroll
        for (int j = 1; j < NOUT; j++) outv = (lane == j) ? acc0[j] : outv;
        Z2T[(size_t)t0 * R2 + b * NOUT + lane] = outv;
    }
    if (ok1 && lane < NOUT) {
        float outv = acc1[0];
#pragma unroll
        for (int j = 1; j < NOUT; j++) outv = (lane == j) ? acc1[j] : outv;
        Z2T[(size_t)t1 * R2 + b * NOUT + lane] = outv;
    }
}

// ---------------------------------------------------------------------------
extern "C" void kernel_launch(void* const* d_in, const int* in_sizes, int n_in,
                              void* d_out, int out_size)
{
    const float* spikeInput = (const float*)d_in[0];  // [32, 2312, 350]
    const float* W1         = (const float*)d_in[1];  // [512, 2312]
    const float* W2         = (const float*)d_in[2];  // [10, 512]
    float*       out        = (float*)d_out;          // [32, 10, 350]

    float *y1p, *s1p, *z2p;
    cudaGetSymbolAddress((void**)&y1p, g_y1);
    cudaGetSymbolAddress((void**)&s1p, g_s1);
    cudaGetSymbolAddress((void**)&z2p, g_z2);

    // #1: fused transpose + index build
    prep_kernel<<<NTRB + NBLB, 256>>>(W1, spikeInput);

    // #2: sparse gather-accumulate (dominant, at its wall)
    sparse_accum_kernel<<<NCOL, 128>>>();

    // #3: layer-1 scan
    iir_scan_kernel<R1, true><<<R1 / 64, 64>>>(y1p, s1p);

    // #4: dense layer 2 (profiled)
    dim3 g2((T_ + 15) / 16, B_);              // (22, 32) -> 704 blocks
    gemm2_kernel<<<g2, 256>>>(W2, s1p, z2p);

    // #5: layer-2 scan -> final output
    iir_scan_kernel<R2, false><<<R2 / 64, 64>>>(z2p, out);
}